// round 3
// baseline (speedup 1.0000x reference)
#include <cuda_runtime.h>

#define V_MAX 100000

// -------- scratch (static device arrays; no allocation) --------
__device__ float g_h [V_MAX];
__device__ float g_f1[V_MAX * 32];
__device__ float g_h2[V_MAX * 32];
__device__ float g_f2[V_MAX * 64];

// -------- f32x2 packed helpers --------
__device__ __forceinline__ unsigned long long pack2(float lo, float hi) {
    unsigned long long r;
    asm("mov.b64 %0, {%1, %2};" : "=l"(r) : "f"(lo), "f"(hi));
    return r;
}
__device__ __forceinline__ void unpack2(unsigned long long v, float& lo, float& hi) {
    asm("mov.b64 {%0, %1}, %2;" : "=f"(lo), "=f"(hi) : "l"(v));
}
__device__ __forceinline__ unsigned long long fma2(unsigned long long a,
                                                   unsigned long long b,
                                                   unsigned long long c) {
    unsigned long long d;
    asm("fma.rn.f32x2 %0, %1, %2, %3;" : "=l"(d) : "l"(a), "l"(b), "l"(c));
    return d;
}

// ============================================================
// K1: h[v] = mean_n relu(conv_k3(vp[nb1[v,:]]))   (warp per vertex)
// ============================================================
__global__ void k1_h(const float* __restrict__ vp, const int* __restrict__ nb1,
                     const float* __restrict__ wv1, const float* __restrict__ bv1,
                     int V) {
    int warp = (blockIdx.x * blockDim.x + threadIdx.x) >> 5;
    int lane = threadIdx.x & 31;
    if (warp >= V) return;
    int j = nb1[warp * 32 + lane];
    if ((unsigned)j >= (unsigned)V) j = 0;      // defensive clamp
    float g = vp[j];
    float w0 = __ldg(wv1 + 0), w1 = __ldg(wv1 + 1), w2 = __ldg(wv1 + 2);
    float b  = __ldg(bv1);
    float gm = __shfl_up_sync(0xffffffffu, g, 1);
    if (lane == 0) gm = 0.f;
    float gp = __shfl_down_sync(0xffffffffu, g, 1);
    if (lane == 31) gp = 0.f;
    float a = fmaxf(w0 * gm + w1 * g + w2 * gp + b, 0.f);
    #pragma unroll
    for (int s = 16; s > 0; s >>= 1) a += __shfl_xor_sync(0xffffffffu, a, s);
    if (lane == 0) g_h[warp] = a * (1.0f / 32.0f);
}

// ============================================================
// K2: f1[v,o] = h[v-1]*w1[o,0] + h[v]*w1[o,1] + h[v+1]*w1[o,2] + b1[o]
// ============================================================
__global__ void k2_f1(const float* __restrict__ w1, const float* __restrict__ b1,
                      int V) {
    int idx = blockIdx.x * blockDim.x + threadIdx.x;
    int v = idx >> 5, o = idx & 31;
    if (v >= V) return;
    float hm = (v > 0)     ? g_h[v - 1] : 0.f;
    float hc =               g_h[v];
    float hp = (v < V - 1) ? g_h[v + 1] : 0.f;
    g_f1[idx] = hm * __ldg(w1 + o * 3 + 0) + hc * __ldg(w1 + o * 3 + 1)
              + hp * __ldg(w1 + o * 3 + 2) + __ldg(b1 + o);
}

// ============================================================
// K3: h2[v,c] = mean_n relu(conv_k3_over_n( f1[nb2[v,n], c] ))
//     warp per vertex, lane = channel c; neighbor index broadcast via shfl
//     -> each f1-row read is one coalesced 128B load (f1 is L2-resident).
// ============================================================
__global__ void k3_h2(const int* __restrict__ nb2, const float* __restrict__ wv2,
                      const float* __restrict__ bv2, int V) {
    int warp = (blockIdx.x * blockDim.x + threadIdx.x) >> 5;
    int lane = threadIdx.x & 31;
    if (warp >= V) return;
    int idx = nb2[warp * 32 + lane];
    if ((unsigned)idx >= (unsigned)V) idx = 0;  // defensive clamp
    float w0 = __ldg(wv2 + 0), w1 = __ldg(wv2 + 1), w2 = __ldg(wv2 + 2);
    float b  = __ldg(bv2);
    float gm = 0.f;
    int r0 = __shfl_sync(0xffffffffu, idx, 0);
    float gc = g_f1[r0 * 32 + lane];
    float acc = 0.f;
    #pragma unroll
    for (int p = 0; p < 32; p++) {
        float gn = 0.f;
        if (p + 1 < 32) {
            int rn = __shfl_sync(0xffffffffu, idx, p + 1);
            gn = g_f1[rn * 32 + lane];
        }
        acc += fmaxf(w0 * gm + w1 * gc + w2 * gn + b, 0.f);
        gm = gc; gc = gn;
    }
    g_h2[warp * 32 + lane] = acc * (1.0f / 32.0f);
}

// ============================================================
// K4: f2[v,o] = b2[o] + sum_{c,k} h2[v-1+k, c] * w2[o,c,k]
//     512 threads = 8 vertex-groups x 64 outputs. Each group handles
//     EXACTLY ONE vertex (fixes R2's lt-overrun -> shared OOB trap).
//     w2 transposed into smem as [ck][o] (conflict-free LDS).
// ============================================================
#define K4_TILE 8
__global__ __launch_bounds__(512) void k4_f2(const float* __restrict__ w2,
                                             const float* __restrict__ b2, int V) {
    __shared__ float w2s[96 * 64];              // [c*3+k][o]
    __shared__ float sh[(K4_TILE + 2) * 32];    // h2 rows vbase-1 .. vbase+K4_TILE
    int tid = threadIdx.x;
    for (int i = tid; i < 96 * 64; i += 512) {
        int o = i / 96, ck = i % 96;
        w2s[ck * 64 + o] = w2[i];
    }
    int vbase = blockIdx.x * K4_TILE;
    for (int i = tid; i < (K4_TILE + 2) * 32; i += 512) {
        int r = vbase - 1 + (i >> 5);
        sh[i] = (r >= 0 && r < V) ? g_h2[r * 32 + (i & 31)] : 0.f;
    }
    __syncthreads();
    int lt = tid >> 6, o = tid & 63;            // lt in 0..7: one vertex per group
    int v = vbase + lt;
    if (v < V) {
        float acc = __ldg(b2 + o);
        #pragma unroll
        for (int c = 0; c < 32; c++) {
            float hm = sh[(lt + 0) * 32 + c];
            float hc = sh[(lt + 1) * 32 + c];
            float hp = sh[(lt + 2) * 32 + c];
            acc += hm * w2s[(c * 3 + 0) * 64 + o];
            acc += hc * w2s[(c * 3 + 1) * 64 + o];
            acc += hp * w2s[(c * 3 + 2) * 64 + o];
        }
        g_f2[v * 64 + o] = acc;
    }
}

// ============================================================
// K5: logits = f2 @ wfc.T + bfc ; softmax  (the hot kernel)
//     256 threads, thread owns outputs (2t, 2t+1) packed as f32x2.
//     wfc held in 64 packed registers; f2 staged in smem pre-duplicated
//     -> inner loop = 1 LDS.64 + 1 FFMA2 per 2 MACs (fma-pipe bound).
//     4-vertex tile = 4 independent acc chains.
// ============================================================
__global__ __launch_bounds__(256, 1) void k5_fc(const float* __restrict__ wfc,
                                                const float* __restrict__ bfc,
                                                float* __restrict__ out, int V) {
    __shared__ unsigned long long f2s[4 * 64];  // duplicated f2 values
    __shared__ float smax[4 * 8];
    __shared__ float ssum[4 * 8];
    int tid  = threadIdx.x;
    int lane = tid & 31, warp = tid >> 5;

    unsigned long long wpair[64];
    const float* wa = wfc + (2 * tid) * 64;
    const float* wb = wfc + (2 * tid + 1) * 64;
    #pragma unroll
    for (int c = 0; c < 64; c++) wpair[c] = pack2(__ldg(wa + c), __ldg(wb + c));
    unsigned long long bp = pack2(__ldg(bfc + 2 * tid), __ldg(bfc + 2 * tid + 1));

    int lt = tid >> 6, lc = tid & 63;

    for (int vbase = blockIdx.x * 4; vbase < V; vbase += gridDim.x * 4) {
        int vl = vbase + lt;
        float fv = (vl < V) ? g_f2[vl * 64 + lc] : 0.f;
        f2s[tid] = pack2(fv, fv);
        __syncthreads();

        unsigned long long a0 = bp, a1 = bp, a2 = bp, a3 = bp;
        #pragma unroll
        for (int c = 0; c < 64; c++) {
            a0 = fma2(wpair[c], f2s[0 * 64 + c], a0);
            a1 = fma2(wpair[c], f2s[1 * 64 + c], a1);
            a2 = fma2(wpair[c], f2s[2 * 64 + c], a2);
            a3 = fma2(wpair[c], f2s[3 * 64 + c], a3);
        }
        float l0[4], l1[4];
        unpack2(a0, l0[0], l1[0]);
        unpack2(a1, l0[1], l1[1]);
        unpack2(a2, l0[2], l1[2]);
        unpack2(a3, l0[3], l1[3]);

        // phase A: per-warp max
        #pragma unroll
        for (int t = 0; t < 4; t++) {
            float m = fmaxf(l0[t], l1[t]);
            #pragma unroll
            for (int s = 16; s > 0; s >>= 1) m = fmaxf(m, __shfl_xor_sync(0xffffffffu, m, s));
            if (lane == 0) smax[t * 8 + warp] = m;
        }
        __syncthreads();

        // phase B: block max -> exp -> per-warp sum
        float e0[4], e1[4];
        #pragma unroll
        for (int t = 0; t < 4; t++) {
            float bm = smax[t * 8];
            #pragma unroll
            for (int j = 1; j < 8; j++) bm = fmaxf(bm, smax[t * 8 + j]);
            e0[t] = __expf(l0[t] - bm);
            e1[t] = __expf(l1[t] - bm);
            float s = e0[t] + e1[t];
            #pragma unroll
            for (int sh = 16; sh > 0; sh >>= 1) s += __shfl_xor_sync(0xffffffffu, s, sh);
            if (lane == 0) ssum[t * 8 + warp] = s;
        }
        __syncthreads();

        // phase C: block sum -> normalize -> store (float2, coalesced)
        #pragma unroll
        for (int t = 0; t < 4; t++) {
            int v = vbase + t;
            if (v < V) {
                float bs = ssum[t * 8];
                #pragma unroll
                for (int j = 1; j < 8; j++) bs += ssum[t * 8 + j];
                float inv = 1.0f / bs;
                ((float2*)out)[v * 256 + tid] = make_float2(e0[t] * inv, e1[t] * inv);
            }
        }
        __syncthreads();
    }
}

// ============================================================
// Launch: bind inputs BY ELEMENT COUNT (robust to metadata ordering).
//   vp:V  nb1:32V  nb2:32V  wv1:3  bv1:1  w1:96  b1:32
//   wv2:3 bv2:1    w2:6144  b2:64  wfc:32768  bfc:512
// ============================================================
extern "C" void kernel_launch(void* const* d_in, const int* in_sizes, int n_in,
                              void* d_out, int out_size) {
    long long mx = 0;
    for (int i = 0; i < n_in; i++) if ((long long)in_sizes[i] > mx) mx = in_sizes[i];
    int V = (int)(mx / 32);
    if (V > V_MAX) V = V_MAX;

    const float *vp = 0, *wv1 = 0, *bv1 = 0, *w1 = 0, *b1 = 0;
    const float *wv2 = 0, *bv2 = 0, *w2 = 0, *b2 = 0, *wfc = 0, *bfc = 0;
    const int *nb1 = 0, *nb2 = 0;

    int nb_seen = 0, wv_seen = 0, bv_seen = 0;
    for (int i = 0; i < n_in; i++) {
        long long s = in_sizes[i];
        const void* p = d_in[i];
        if (s == mx)            { if (nb_seen++ == 0) nb1 = (const int*)p; else nb2 = (const int*)p; }
        else if (s == V)        { vp  = (const float*)p; }
        else if (s == 3)        { if (wv_seen++ == 0) wv1 = (const float*)p; else wv2 = (const float*)p; }
        else if (s == 1)        { if (bv_seen++ == 0) bv1 = (const float*)p; else bv2 = (const float*)p; }
        else if (s == 96)       { w1  = (const float*)p; }
        else if (s == 32)       { b1  = (const float*)p; }
        else if (s == 6144)     { w2  = (const float*)p; }
        else if (s == 64)       { b2  = (const float*)p; }
        else if (s == 32768)    { wfc = (const float*)p; }
        else if (s == 512)      { bfc = (const float*)p; }
    }
    // Binding failure -> do nothing: poisoned output yields clean rel_err
    // diagnostic instead of a null-deref crash.
    if (!vp || !nb1 || !nb2 || !wv1 || !bv1 || !w1 || !b1 ||
        !wv2 || !bv2 || !w2 || !b2 || !wfc || !bfc) return;
    float* out = (float*)d_out;

    int warpBlocks = (V + 7) / 8;                 // 8 warps (256 thr) per block
    k1_h <<<warpBlocks, 256>>>(vp, nb1, wv1, bv1, V);
    k2_f1<<<(V * 32 + 255) / 256, 256>>>(w1, b1, V);
    k3_h2<<<warpBlocks, 256>>>(nb2, wv2, bv2, V);
    k4_f2<<<(V + K4_TILE - 1) / K4_TILE, 512>>>(w2, b2, V);
    k5_fc<<<148, 256>>>(wfc, bfc, out, V);
}

// round 6
// speedup vs baseline: 1.2989x; 1.2989x over previous
#include <cuda_runtime.h>

#define V_MAX 100000

// -------- scratch (static device arrays; no allocation) --------
__device__ float g_h [V_MAX];
__device__ float g_f1[V_MAX * 32];
__device__ float g_h2[V_MAX * 32];
__device__ float g_f2[V_MAX * 64];

// -------- f32x2 packed helpers --------
__device__ __forceinline__ unsigned long long pack2(float lo, float hi) {
    unsigned long long r;
    asm("mov.b64 %0, {%1, %2};" : "=l"(r) : "f"(lo), "f"(hi));
    return r;
}
__device__ __forceinline__ void unpack2(unsigned long long v, float& lo, float& hi) {
    asm("mov.b64 {%0, %1}, %2;" : "=f"(lo), "=f"(hi) : "l"(v));
}
__device__ __forceinline__ unsigned long long fma2(unsigned long long a,
                                                   unsigned long long b,
                                                   unsigned long long c) {
    unsigned long long d;
    asm("fma.rn.f32x2 %0, %1, %2, %3;" : "=l"(d) : "l"(a), "l"(b), "l"(c));
    return d;
}

// ============================================================
// K1: h[v] = mean_n relu(conv_k3(vp[nb1[v,:]]))   (warp per vertex)
// ============================================================
__global__ void k1_h(const float* __restrict__ vp, const int* __restrict__ nb1,
                     const float* __restrict__ wv1, const float* __restrict__ bv1,
                     int V) {
    int warp = (blockIdx.x * blockDim.x + threadIdx.x) >> 5;
    int lane = threadIdx.x & 31;
    if (warp >= V) return;
    int j = nb1[warp * 32 + lane];
    if ((unsigned)j >= (unsigned)V) j = 0;      // defensive clamp
    float g = vp[j];
    float w0 = __ldg(wv1 + 0), w1 = __ldg(wv1 + 1), w2 = __ldg(wv1 + 2);
    float b  = __ldg(bv1);
    float gm = __shfl_up_sync(0xffffffffu, g, 1);
    if (lane == 0) gm = 0.f;
    float gp = __shfl_down_sync(0xffffffffu, g, 1);
    if (lane == 31) gp = 0.f;
    float a = fmaxf(w0 * gm + w1 * g + w2 * gp + b, 0.f);
    #pragma unroll
    for (int s = 16; s > 0; s >>= 1) a += __shfl_xor_sync(0xffffffffu, a, s);
    if (lane == 0) g_h[warp] = a * (1.0f / 32.0f);
}

// ============================================================
// K2: f1[v,o] = h[v-1]*w1[o,0] + h[v]*w1[o,1] + h[v+1]*w1[o,2] + b1[o]
// ============================================================
__global__ void k2_f1(const float* __restrict__ w1, const float* __restrict__ b1,
                      int V) {
    int idx = blockIdx.x * blockDim.x + threadIdx.x;
    int v = idx >> 5, o = idx & 31;
    if (v >= V) return;
    float hm = (v > 0)     ? g_h[v - 1] : 0.f;
    float hc =               g_h[v];
    float hp = (v < V - 1) ? g_h[v + 1] : 0.f;
    g_f1[idx] = hm * __ldg(w1 + o * 3 + 0) + hc * __ldg(w1 + o * 3 + 1)
              + hp * __ldg(w1 + o * 3 + 2) + __ldg(b1 + o);
}

// ============================================================
// K3: h2[v,c] = mean_n relu(conv_k3_over_n( f1[nb2[v,n], c] ))
//     warp per vertex, lane = channel c; neighbor index broadcast via shfl
//     -> each f1-row read is one coalesced 128B load (f1 is L2-resident).
// ============================================================
__global__ void k3_h2(const int* __restrict__ nb2, const float* __restrict__ wv2,
                      const float* __restrict__ bv2, int V) {
    int warp = (blockIdx.x * blockDim.x + threadIdx.x) >> 5;
    int lane = threadIdx.x & 31;
    if (warp >= V) return;
    int idx = nb2[warp * 32 + lane];
    if ((unsigned)idx >= (unsigned)V) idx = 0;  // defensive clamp
    float w0 = __ldg(wv2 + 0), w1 = __ldg(wv2 + 1), w2 = __ldg(wv2 + 2);
    float b  = __ldg(bv2);
    float gm = 0.f;
    int r0 = __shfl_sync(0xffffffffu, idx, 0);
    float gc = g_f1[r0 * 32 + lane];
    float acc = 0.f;
    #pragma unroll
    for (int p = 0; p < 32; p++) {
        float gn = 0.f;
        if (p + 1 < 32) {
            int rn = __shfl_sync(0xffffffffu, idx, p + 1);
            gn = g_f1[rn * 32 + lane];
        }
        acc += fmaxf(w0 * gm + w1 * gc + w2 * gn + b, 0.f);
        gm = gc; gc = gn;
    }
    g_h2[warp * 32 + lane] = acc * (1.0f / 32.0f);
}

// ============================================================
// K4 (rewritten): f2[v,o] = b2[o] + sum_{c,k} h2[v-1+k,c] * w2[o,c,k]
//   Thread owns output o, holds all 96 weights in 48 f32x2 registers.
//   Rolling-dot trick: per h2 row compute d0/d1/d2 = dot(row, W0/W1/W2)
//   ONCE, emit f2[v] = d0[v-1] + d1[v] + d2[v+1] + b.
//   Row loads are warp-uniform broadcast LDG.128 (L1/L2-resident h2).
//   No shared memory, no __syncthreads, no per-block weight staging.
// ============================================================
#define K4_GROUPS 4     // vertex groups per 256-thread block
#define K4_STRIP  64    // vertices per group

__device__ __forceinline__ void k4_row_dots(
    int r, int V,
    const unsigned long long* wp0, const unsigned long long* wp1,
    const unsigned long long* wp2,
    float& e0, float& e1, float& e2)
{
    if ((unsigned)r >= (unsigned)V) { e0 = 0.f; e1 = 0.f; e2 = 0.f; return; }
    const float4* row = (const float4*)(g_h2 + (size_t)r * 32);
    unsigned long long a0 = 0ull, a1 = 0ull, a2 = 0ull;
    #pragma unroll
    for (int q = 0; q < 8; q++) {
        float4 f = __ldg(row + q);                  // broadcast (warp-uniform)
        unsigned long long hxy = pack2(f.x, f.y);   // c-pair 2q
        unsigned long long hzw = pack2(f.z, f.w);   // c-pair 2q+1
        a0 = fma2(hxy, wp0[2 * q], a0);  a0 = fma2(hzw, wp0[2 * q + 1], a0);
        a1 = fma2(hxy, wp1[2 * q], a1);  a1 = fma2(hzw, wp1[2 * q + 1], a1);
        a2 = fma2(hxy, wp2[2 * q], a2);  a2 = fma2(hzw, wp2[2 * q + 1], a2);
    }
    float lo, hi;
    unpack2(a0, lo, hi); e0 = lo + hi;
    unpack2(a1, lo, hi); e1 = lo + hi;
    unpack2(a2, lo, hi); e2 = lo + hi;
}

__global__ __launch_bounds__(256) void k4_f2(const float* __restrict__ w2,
                                             const float* __restrict__ b2, int V) {
    int tid = threadIdx.x;
    int grp = tid >> 6, o = tid & 63;

    // Pack weights over c-pairs: wpK[c2] = (w2[o][2c2][K], w2[o][2c2+1][K])
    unsigned long long wp0[16], wp1[16], wp2[16];
    const float* wo = w2 + o * 96;                  // w2 layout [o][c][k]
    #pragma unroll
    for (int c2 = 0; c2 < 16; c2++) {
        wp0[c2] = pack2(__ldg(wo + 6 * c2 + 0), __ldg(wo + 6 * c2 + 3));
        wp1[c2] = pack2(__ldg(wo + 6 * c2 + 1), __ldg(wo + 6 * c2 + 4));
        wp2[c2] = pack2(__ldg(wo + 6 * c2 + 2), __ldg(wo + 6 * c2 + 5));
    }
    float bias = __ldg(b2 + o);

    int vbase = (blockIdx.x * K4_GROUPS + grp) * K4_STRIP;
    if (vbase >= V) return;
    int vend = vbase + K4_STRIP; if (vend > V) vend = V;

    // Prime the pipeline: d0m = d0(row vbase-1), d0c/d1c = dots of row vbase.
    float d0m, d1x, d2x, d0c, d1c;
    k4_row_dots(vbase - 1, V, wp0, wp1, wp2, d0m, d1x, d2x);
    k4_row_dots(vbase,     V, wp0, wp1, wp2, d0c, d1c, d2x);

    for (int v = vbase; v < vend; v++) {
        float e0, e1, e2;
        k4_row_dots(v + 1, V, wp0, wp1, wp2, e0, e1, e2);
        g_f2[(size_t)v * 64 + o] = d0m + d1c + e2 + bias;
        d0m = d0c; d0c = e0; d1c = e1;
    }
}

// ============================================================
// K5: logits = f2 @ wfc.T + bfc ; softmax  (the hot kernel)
//     256 threads, thread owns outputs (2t, 2t+1) packed as f32x2.
//     wfc in 64 packed registers; f2 staged in smem pre-duplicated;
//     inner loop now LDS.128 (2 packed values) + 2 FFMA2 per c-pair.
//     4-vertex tile = 4 independent acc chains.
// ============================================================
__global__ __launch_bounds__(256, 1) void k5_fc(const float* __restrict__ wfc,
                                                const float* __restrict__ bfc,
                                                float* __restrict__ out, int V) {
    __shared__ __align__(16) unsigned long long f2s[4 * 64];  // duplicated f2
    __shared__ float smax[4 * 8];
    __shared__ float ssum[4 * 8];
    int tid  = threadIdx.x;
    int lane = tid & 31, warp = tid >> 5;

    unsigned long long wpair[64];
    const float* wa = wfc + (2 * tid) * 64;
    const float* wb = wfc + (2 * tid + 1) * 64;
    #pragma unroll
    for (int c = 0; c < 64; c++) wpair[c] = pack2(__ldg(wa + c), __ldg(wb + c));
    unsigned long long bp = pack2(__ldg(bfc + 2 * tid), __ldg(bfc + 2 * tid + 1));

    int lt = tid >> 6, lc = tid & 63;

    for (int vbase = blockIdx.x * 4; vbase < V; vbase += gridDim.x * 4) {
        int vl = vbase + lt;
        float fv = (vl < V) ? g_f2[(size_t)vl * 64 + lc] : 0.f;
        f2s[tid] = pack2(fv, fv);
        __syncthreads();

        unsigned long long a0 = bp, a1 = bp, a2 = bp, a3 = bp;
        #pragma unroll
        for (int c = 0; c < 64; c += 2) {
            ulonglong2 q0 = *(const ulonglong2*)&f2s[0 * 64 + c];
            ulonglong2 q1 = *(const ulonglong2*)&f2s[1 * 64 + c];
            ulonglong2 q2 = *(const ulonglong2*)&f2s[2 * 64 + c];
            ulonglong2 q3 = *(const ulonglong2*)&f2s[3 * 64 + c];
            a0 = fma2(wpair[c], q0.x, a0);  a0 = fma2(wpair[c + 1], q0.y, a0);
            a1 = fma2(wpair[c], q1.x, a1);  a1 = fma2(wpair[c + 1], q1.y, a1);
            a2 = fma2(wpair[c], q2.x, a2);  a2 = fma2(wpair[c + 1], q2.y, a2);
            a3 = fma2(wpair[c], q3.x, a3);  a3 = fma2(wpair[c + 1], q3.y, a3);
        }
        float l0[4], l1[4];
        unpack2(a0, l0[0], l1[0]);
        unpack2(a1, l0[1], l1[1]);
        unpack2(a2, l0[2], l1[2]);
        unpack2(a3, l0[3], l1[3]);

        // phase A: per-warp max
        #pragma unroll
        for (int t = 0; t < 4; t++) {
            float m = fmaxf(l0[t], l1[t]);
            #pragma unroll
            for (int s = 16; s > 0; s >>= 1) m = fmaxf(m, __shfl_xor_sync(0xffffffffu, m, s));
            if (lane == 0) smax[t * 8 + warp] = m;
        }
        __syncthreads();

        // phase B: block max -> exp -> per-warp sum
        float e0[4], e1[4];
        #pragma unroll
        for (int t = 0; t < 4; t++) {
            float bm = smax[t * 8];
            #pragma unroll
            for (int j = 1; j < 8; j++) bm = fmaxf(bm, smax[t * 8 + j]);
            e0[t] = __expf(l0[t] - bm);
            e1[t] = __expf(l1[t] - bm);
            float s = e0[t] + e1[t];
            #pragma unroll
            for (int sh = 16; sh > 0; sh >>= 1) s += __shfl_xor_sync(0xffffffffu, s, sh);
            if (lane == 0) ssum[t * 8 + warp] = s;
        }
        __syncthreads();

        // phase C: block sum -> normalize -> store (float2, coalesced)
        #pragma unroll
        for (int t = 0; t < 4; t++) {
            int v = vbase + t;
            if (v < V) {
                float bs = ssum[t * 8];
                #pragma unroll
                for (int j = 1; j < 8; j++) bs += ssum[t * 8 + j];
                float inv = 1.0f / bs;
                ((float2*)out)[(size_t)v * 256 + tid] = make_float2(e0[t] * inv, e1[t] * inv);
            }
        }
        __syncthreads();
    }
}

// ============================================================
// Launch: bind inputs BY ELEMENT COUNT (robust to metadata ordering).
// ============================================================
extern "C" void kernel_launch(void* const* d_in, const int* in_sizes, int n_in,
                              void* d_out, int out_size) {
    long long mx = 0;
    for (int i = 0; i < n_in; i++) if ((long long)in_sizes[i] > mx) mx = in_sizes[i];
    int V = (int)(mx / 32);
    if (V > V_MAX) V = V_MAX;

    const float *vp = 0, *wv1 = 0, *bv1 = 0, *w1 = 0, *b1 = 0;
    const float *wv2 = 0, *bv2 = 0, *w2 = 0, *b2 = 0, *wfc = 0, *bfc = 0;
    const int *nb1 = 0, *nb2 = 0;

    int nb_seen = 0, wv_seen = 0, bv_seen = 0;
    for (int i = 0; i < n_in; i++) {
        long long s = in_sizes[i];
        const void* p = d_in[i];
        if (s == mx)            { if (nb_seen++ == 0) nb1 = (const int*)p; else nb2 = (const int*)p; }
        else if (s == V)        { vp  = (const float*)p; }
        else if (s == 3)        { if (wv_seen++ == 0) wv1 = (const float*)p; else wv2 = (const float*)p; }
        else if (s == 1)        { if (bv_seen++ == 0) bv1 = (const float*)p; else bv2 = (const float*)p; }
        else if (s == 96)       { w1  = (const float*)p; }
        else if (s == 32)       { b1  = (const float*)p; }
        else if (s == 6144)     { w2  = (const float*)p; }
        else if (s == 64)       { b2  = (const float*)p; }
        else if (s == 32768)    { wfc = (const float*)p; }
        else if (s == 512)      { bfc = (const float*)p; }
    }
    if (!vp || !nb1 || !nb2 || !wv1 || !bv1 || !w1 || !b1 ||
        !wv2 || !bv2 || !w2 || !b2 || !wfc || !bfc) return;
    float* out = (float*)d_out;

    int warpBlocks = (V + 7) / 8;                 // 8 warps (256 thr) per block
    int k4Blocks = (V + K4_GROUPS * K4_STRIP - 1) / (K4_GROUPS * K4_STRIP);
    k1_h <<<warpBlocks, 256>>>(vp, nb1, wv1, bv1, V);
    k2_f1<<<(V * 32 + 255) / 256, 256>>>(w1, b1, V);
    k3_h2<<<warpBlocks, 256>>>(nb2, wv2, bv2, V);
    k4_f2<<<k4Blocks, 256>>>(w2, b2, V);
    k5_fc<<<148, 256>>>(wfc, bfc, out, V);
}

// round 11
// speedup vs baseline: 1.3340x; 1.0270x over previous
#include <cuda_runtime.h>

#define V_MAX 100000

// -------- scratch (static device arrays; no allocation) --------
__device__ float g_h [V_MAX];
__device__ float g_f1[V_MAX * 32];
__device__ float g_h2[V_MAX * 32];
__device__ float g_f2p[4][V_MAX * 64];   // k4 partial sums (channel quarters)

// -------- f32x2 packed helpers --------
__device__ __forceinline__ unsigned long long pack2(float lo, float hi) {
    unsigned long long r;
    asm("mov.b64 %0, {%1, %2};" : "=l"(r) : "f"(lo), "f"(hi));
    return r;
}
__device__ __forceinline__ void unpack2(unsigned long long v, float& lo, float& hi) {
    asm("mov.b64 {%0, %1}, %2;" : "=f"(lo), "=f"(hi) : "l"(v));
}
__device__ __forceinline__ unsigned long long fma2(unsigned long long a,
                                                   unsigned long long b,
                                                   unsigned long long c) {
    unsigned long long d;
    asm("fma.rn.f32x2 %0, %1, %2, %3;" : "=l"(d) : "l"(a), "l"(b), "l"(c));
    return d;
}

// ============================================================
// K1: h[v] = mean_n relu(conv_k3(vp[nb1[v,:]]))   (warp per vertex)
// ============================================================
__global__ void k1_h(const float* __restrict__ vp, const int* __restrict__ nb1,
                     const float* __restrict__ wv1, const float* __restrict__ bv1,
                     int V) {
    int warp = (blockIdx.x * blockDim.x + threadIdx.x) >> 5;
    int lane = threadIdx.x & 31;
    if (warp >= V) return;
    int j = nb1[warp * 32 + lane];
    if ((unsigned)j >= (unsigned)V) j = 0;      // defensive clamp
    float g = vp[j];
    float w0 = __ldg(wv1 + 0), w1 = __ldg(wv1 + 1), w2 = __ldg(wv1 + 2);
    float b  = __ldg(bv1);
    float gm = __shfl_up_sync(0xffffffffu, g, 1);
    if (lane == 0) gm = 0.f;
    float gp = __shfl_down_sync(0xffffffffu, g, 1);
    if (lane == 31) gp = 0.f;
    float a = fmaxf(w0 * gm + w1 * g + w2 * gp + b, 0.f);
    #pragma unroll
    for (int s = 16; s > 0; s >>= 1) a += __shfl_xor_sync(0xffffffffu, a, s);
    if (lane == 0) g_h[warp] = a * (1.0f / 32.0f);
}

// ============================================================
// K2: f1[v,o] = h[v-1]*w1[o,0] + h[v]*w1[o,1] + h[v+1]*w1[o,2] + b1[o]
// ============================================================
__global__ void k2_f1(const float* __restrict__ w1, const float* __restrict__ b1,
                      int V) {
    int idx = blockIdx.x * blockDim.x + threadIdx.x;
    int v = idx >> 5, o = idx & 31;
    if (v >= V) return;
    float hm = (v > 0)     ? g_h[v - 1] : 0.f;
    float hc =               g_h[v];
    float hp = (v < V - 1) ? g_h[v + 1] : 0.f;
    g_f1[idx] = hm * __ldg(w1 + o * 3 + 0) + hc * __ldg(w1 + o * 3 + 1)
              + hp * __ldg(w1 + o * 3 + 2) + __ldg(b1 + o);
}

// ============================================================
// K3: h2[v,c] = mean_n relu(conv_k3_over_n( f1[nb2[v,n], c] ))
//     warp per vertex, lane = channel c. ALL 32 row loads issued upfront
//     into a register file array (MLP=32), conv done from registers.
// ============================================================
__global__ void k3_h2(const int* __restrict__ nb2, const float* __restrict__ wv2,
                      const float* __restrict__ bv2, int V) {
    int warp = (blockIdx.x * blockDim.x + threadIdx.x) >> 5;
    int lane = threadIdx.x & 31;
    if (warp >= V) return;
    int idx = nb2[warp * 32 + lane];
    if ((unsigned)idx >= (unsigned)V) idx = 0;  // defensive clamp

    float gv[32];
    #pragma unroll
    for (int p = 0; p < 32; p++) {
        int rn = __shfl_sync(0xffffffffu, idx, p);
        gv[p] = __ldg(&g_f1[(size_t)rn * 32 + lane]);  // coalesced 128B row
    }
    float w0 = __ldg(wv2 + 0), w1 = __ldg(wv2 + 1), w2 = __ldg(wv2 + 2);
    float b  = __ldg(bv2);
    float acc = 0.f;
    #pragma unroll
    for (int p = 0; p < 32; p++) {
        float gm = (p > 0)  ? gv[p - 1] : 0.f;
        float gp = (p < 31) ? gv[p + 1] : 0.f;
        acc += fmaxf(w0 * gm + w1 * gv[p] + w2 * gp + b, 0.f);
    }
    g_h2[(size_t)warp * 32 + lane] = acc * (1.0f / 32.0f);
}

// ============================================================
// K4: f2[v,o] = b2[o] + sum_{c,k} h2[v-1+k,c] * w2[o,c,k]
//   4-way channel split: thread owns (o, quarter q = 8 channels).
//   Only 12 packed weight regs -> ~60 regs -> 3+ blocks/SM (occ up from 21%).
//   Rolling-dot: each h2 row's three tap-dots computed once; partials
//   written to g_f2p[q], summed in k5's staging read.
// ============================================================
#define K4_STRIP 64

__device__ __forceinline__ void k4q_dots(
    int r, int V, int q,
    const unsigned long long* wp0, const unsigned long long* wp1,
    const unsigned long long* wp2,
    float& e0, float& e1, float& e2)
{
    if ((unsigned)r >= (unsigned)V) { e0 = 0.f; e1 = 0.f; e2 = 0.f; return; }
    const float4* row = (const float4*)(g_h2 + (size_t)r * 32 + q * 8);
    float4 fa = __ldg(row);          // channels 8q+0..3 (broadcast, warp-uniform)
    float4 fb = __ldg(row + 1);      // channels 8q+4..7
    unsigned long long h0 = pack2(fa.x, fa.y);
    unsigned long long h1 = pack2(fa.z, fa.w);
    unsigned long long h2 = pack2(fb.x, fb.y);
    unsigned long long h3 = pack2(fb.z, fb.w);
    unsigned long long a0 = fma2(h0, wp0[0], 0ull);
    unsigned long long a1 = fma2(h0, wp1[0], 0ull);
    unsigned long long a2 = fma2(h0, wp2[0], 0ull);
    a0 = fma2(h1, wp0[1], a0);  a1 = fma2(h1, wp1[1], a1);  a2 = fma2(h1, wp2[1], a2);
    a0 = fma2(h2, wp0[2], a0);  a1 = fma2(h2, wp1[2], a1);  a2 = fma2(h2, wp2[2], a2);
    a0 = fma2(h3, wp0[3], a0);  a1 = fma2(h3, wp1[3], a1);  a2 = fma2(h3, wp2[3], a2);
    float lo, hi;
    unpack2(a0, lo, hi); e0 = lo + hi;
    unpack2(a1, lo, hi); e1 = lo + hi;
    unpack2(a2, lo, hi); e2 = lo + hi;
}

__global__ __launch_bounds__(256, 3) void k4_f2(const float* __restrict__ w2,
                                                const float* __restrict__ b2, int V) {
    int tid = threadIdx.x;
    int o = tid & 63;
    int q = tid >> 6;                            // channel quarter 0..3

    // wpK[j] = (w2[o][8q+2j][K], w2[o][8q+2j+1][K]); w2 layout [o][c][k]
    const float* wo = w2 + o * 96 + q * 24;
    unsigned long long wp0[4], wp1[4], wp2[4];
    #pragma unroll
    for (int j = 0; j < 4; j++) {
        wp0[j] = pack2(__ldg(wo + 6 * j + 0), __ldg(wo + 6 * j + 3));
        wp1[j] = pack2(__ldg(wo + 6 * j + 1), __ldg(wo + 6 * j + 4));
        wp2[j] = pack2(__ldg(wo + 6 * j + 2), __ldg(wo + 6 * j + 5));
    }
    float bias = (q == 0) ? __ldg(b2 + o) : 0.f;
    float* outbuf = g_f2p[q];

    int vbase = blockIdx.x * K4_STRIP;
    if (vbase >= V) return;
    int vend = vbase + K4_STRIP; if (vend > V) vend = V;

    // Prime: d0m = tap0-dot(row vbase-1); d0c/d1c = tap0/tap1 dots(row vbase)
    float d0m, d0c, d1c, tA, tB;
    k4q_dots(vbase - 1, V, q, wp0, wp1, wp2, d0m, tA, tB);
    k4q_dots(vbase,     V, q, wp0, wp1, wp2, d0c, d1c, tB);

    #pragma unroll 4
    for (int v = vbase; v < vend; v++) {
        float e0, e1, e2;
        k4q_dots(v + 1, V, q, wp0, wp1, wp2, e0, e1, e2);
        outbuf[(size_t)v * 64 + o] = d0m + d1c + e2 + bias;
        d0m = d0c; d0c = e0; d1c = e1;
    }
}

// ============================================================
// K5: logits = f2 @ wfc.T + bfc ; softmax
//     Staging read sums the 4 k4 partial buffers.
//     Inner loop: LDS.128 + FFMA2 (fma-pipe bound).
// ============================================================
__global__ __launch_bounds__(256, 1) void k5_fc(const float* __restrict__ wfc,
                                                const float* __restrict__ bfc,
                                                float* __restrict__ out, int V) {
    __shared__ __align__(16) unsigned long long f2s[4 * 64];  // duplicated f2
    __shared__ float smax[4 * 8];
    __shared__ float ssum[4 * 8];
    int tid  = threadIdx.x;
    int lane = tid & 31, warp = tid >> 5;

    unsigned long long wpair[64];
    const float* wa = wfc + (2 * tid) * 64;
    const float* wb = wfc + (2 * tid + 1) * 64;
    #pragma unroll
    for (int c = 0; c < 64; c++) wpair[c] = pack2(__ldg(wa + c), __ldg(wb + c));
    unsigned long long bp = pack2(__ldg(bfc + 2 * tid), __ldg(bfc + 2 * tid + 1));

    int lt = tid >> 6, lc = tid & 63;

    for (int vbase = blockIdx.x * 4; vbase < V; vbase += gridDim.x * 4) {
        int vl = vbase + lt;
        float fv = 0.f;
        if (vl < V) {
            size_t i = (size_t)vl * 64 + lc;
            fv = g_f2p[0][i] + g_f2p[1][i] + g_f2p[2][i] + g_f2p[3][i];
        }
        f2s[tid] = pack2(fv, fv);
        __syncthreads();

        unsigned long long a0 = bp, a1 = bp, a2 = bp, a3 = bp;
        #pragma unroll
        for (int c = 0; c < 64; c += 2) {
            ulonglong2 q0 = *(const ulonglong2*)&f2s[0 * 64 + c];
            ulonglong2 q1 = *(const ulonglong2*)&f2s[1 * 64 + c];
            ulonglong2 q2 = *(const ulonglong2*)&f2s[2 * 64 + c];
            ulonglong2 q3 = *(const ulonglong2*)&f2s[3 * 64 + c];
            a0 = fma2(wpair[c], q0.x, a0);  a0 = fma2(wpair[c + 1], q0.y, a0);
            a1 = fma2(wpair[c], q1.x, a1);  a1 = fma2(wpair[c + 1], q1.y, a1);
            a2 = fma2(wpair[c], q2.x, a2);  a2 = fma2(wpair[c + 1], q2.y, a2);
            a3 = fma2(wpair[c], q3.x, a3);  a3 = fma2(wpair[c + 1], q3.y, a3);
        }
        float l0[4], l1[4];
        unpack2(a0, l0[0], l1[0]);
        unpack2(a1, l0[1], l1[1]);
        unpack2(a2, l0[2], l1[2]);
        unpack2(a3, l0[3], l1[3]);

        // phase A: per-warp max
        #pragma unroll
        for (int t = 0; t < 4; t++) {
            float m = fmaxf(l0[t], l1[t]);
            #pragma unroll
            for (int s = 16; s > 0; s >>= 1) m = fmaxf(m, __shfl_xor_sync(0xffffffffu, m, s));
            if (lane == 0) smax[t * 8 + warp] = m;
        }
        __syncthreads();

        // phase B: block max -> exp -> per-warp sum
        float e0[4], e1[4];
        #pragma unroll
        for (int t = 0; t < 4; t++) {
            float bm = smax[t * 8];
            #pragma unroll
            for (int j = 1; j < 8; j++) bm = fmaxf(bm, smax[t * 8 + j]);
            e0[t] = __expf(l0[t] - bm);
            e1[t] = __expf(l1[t] - bm);
            float s = e0[t] + e1[t];
            #pragma unroll
            for (int sh = 16; sh > 0; sh >>= 1) s += __shfl_xor_sync(0xffffffffu, s, sh);
            if (lane == 0) ssum[t * 8 + warp] = s;
        }
        __syncthreads();

        // phase C: block sum -> normalize -> store (float2, coalesced)
        #pragma unroll
        for (int t = 0; t < 4; t++) {
            int v = vbase + t;
            if (v < V) {
                float bs = ssum[t * 8];
                #pragma unroll
                for (int j = 1; j < 8; j++) bs += ssum[t * 8 + j];
                float inv = 1.0f / bs;
                ((float2*)out)[(size_t)v * 256 + tid] = make_float2(e0[t] * inv, e1[t] * inv);
            }
        }
        __syncthreads();
    }
}

// ============================================================
// Launch: bind inputs BY ELEMENT COUNT (robust to metadata ordering).
// ============================================================
extern "C" void kernel_launch(void* const* d_in, const int* in_sizes, int n_in,
                              void* d_out, int out_size) {
    long long mx = 0;
    for (int i = 0; i < n_in; i++) if ((long long)in_sizes[i] > mx) mx = in_sizes[i];
    int V = (int)(mx / 32);
    if (V > V_MAX) V = V_MAX;

    const float *vp = 0, *wv1 = 0, *bv1 = 0, *w1 = 0, *b1 = 0;
    const float *wv2 = 0, *bv2 = 0, *w2 = 0, *b2 = 0, *wfc = 0, *bfc = 0;
    const int *nb1 = 0, *nb2 = 0;

    int nb_seen = 0, wv_seen = 0, bv_seen = 0;
    for (int i = 0; i < n_in; i++) {
        long long s = in_sizes[i];
        const void* p = d_in[i];
        if (s == mx)            { if (nb_seen++ == 0) nb1 = (const int*)p; else nb2 = (const int*)p; }
        else if (s == V)        { vp  = (const float*)p; }
        else if (s == 3)        { if (wv_seen++ == 0) wv1 = (const float*)p; else wv2 = (const float*)p; }
        else if (s == 1)        { if (bv_seen++ == 0) bv1 = (const float*)p; else bv2 = (const float*)p; }
        else if (s == 96)       { w1  = (const float*)p; }
        else if (s == 32)       { b1  = (const float*)p; }
        else if (s == 6144)     { w2  = (const float*)p; }
        else if (s == 64)       { b2  = (const float*)p; }
        else if (s == 32768)    { wfc = (const float*)p; }
        else if (s == 512)      { bfc = (const float*)p; }
    }
    if (!vp || !nb1 || !nb2 || !wv1 || !bv1 || !w1 || !b1 ||
        !wv2 || !bv2 || !w2 || !b2 || !wfc || !bfc) return;
    float* out = (float*)d_out;

    int warpBlocks = (V + 7) / 8;                 // 8 warps (256 thr) per block
    int k4Blocks = (V + K4_STRIP - 1) / K4_STRIP;
    k1_h <<<warpBlocks, 256>>>(vp, nb1, wv1, bv1, V);
    k2_f1<<<(V * 32 + 255) / 256, 256>>>(w1, b1, V);
    k3_h2<<<warpBlocks, 256>>>(nb2, wv2, bv2, V);
    k4_f2<<<k4Blocks, 256>>>(w2, b2, V);
    k5_fc<<<148, 256>>>(wfc, bfc, out, V);
}

// round 12
// speedup vs baseline: 1.3602x; 1.0196x over previous
#include <cuda_runtime.h>

#define V_MAX 100000

// -------- scratch (static device arrays; no allocation) --------
__device__ float g_f1[V_MAX * 32];
__device__ float g_h2[V_MAX * 32];
__device__ float g_f2p[4][V_MAX * 64];   // k4 partial sums (channel quarters)

// -------- f32x2 packed helpers --------
__device__ __forceinline__ unsigned long long pack2(float lo, float hi) {
    unsigned long long r;
    asm("mov.b64 %0, {%1, %2};" : "=l"(r) : "f"(lo), "f"(hi));
    return r;
}
__device__ __forceinline__ void unpack2(unsigned long long v, float& lo, float& hi) {
    asm("mov.b64 {%0, %1}, %2;" : "=f"(lo), "=f"(hi) : "l"(v));
}
__device__ __forceinline__ unsigned long long fma2(unsigned long long a,
                                                   unsigned long long b,
                                                   unsigned long long c) {
    unsigned long long d;
    asm("fma.rn.f32x2 %0, %1, %2, %3;" : "=l"(d) : "l"(a), "l"(b), "l"(c));
    return d;
}

// ============================================================
// K12 (fused K1+K2): block covers 8 vertices + 2 halo.
//   Warp w (of 10) computes h[vbase-1+w] into smem (redundant across
//   blocks for the halo -> no grid sync needed), then 8 warps emit
//   f1[v, c] = h[v-1]*w1[c,0] + h[v]*w1[c,1] + h[v+1]*w1[c,2] + b1[c].
// ============================================================
#define K12_VPB 8
__global__ __launch_bounds__(320) void k12(const float* __restrict__ vp,
                                           const int* __restrict__ nb1,
                                           const float* __restrict__ wv1,
                                           const float* __restrict__ bv1,
                                           const float* __restrict__ w1,
                                           const float* __restrict__ b1, int V) {
    __shared__ float sh[K12_VPB + 2];
    int tid = threadIdx.x, w = tid >> 5, lane = tid & 31;
    int vbase = blockIdx.x * K12_VPB;
    int vg = vbase - 1 + w;                      // w in 0..9

    float hval = 0.f;
    if ((unsigned)vg < (unsigned)V) {
        int j = nb1[(size_t)vg * 32 + lane];
        if ((unsigned)j >= (unsigned)V) j = 0;   // defensive clamp
        float g = vp[j];
        float c0 = __ldg(wv1 + 0), c1 = __ldg(wv1 + 1), c2 = __ldg(wv1 + 2);
        float b  = __ldg(bv1);
        float gm = __shfl_up_sync(0xffffffffu, g, 1);
        if (lane == 0) gm = 0.f;
        float gp = __shfl_down_sync(0xffffffffu, g, 1);
        if (lane == 31) gp = 0.f;
        float a = fmaxf(c0 * gm + c1 * g + c2 * gp + b, 0.f);
        #pragma unroll
        for (int s = 16; s > 0; s >>= 1) a += __shfl_xor_sync(0xffffffffu, a, s);
        hval = a * (1.0f / 32.0f);
    }
    if (lane == 0) sh[w] = hval;                 // out-of-range vg -> 0 (pad)
    __syncthreads();

    if (tid < 256) {
        int lv = tid >> 5;
        int v = vbase + lv;
        if (v < V) {
            float hm = sh[lv], hc = sh[lv + 1], hp = sh[lv + 2];
            int c = lane;
            g_f1[(size_t)v * 32 + c] =
                hm * __ldg(w1 + c * 3 + 0) + hc * __ldg(w1 + c * 3 + 1)
              + hp * __ldg(w1 + c * 3 + 2) + __ldg(b1 + c);
        }
    }
}

// ============================================================
// K3: h2[v,c] = mean_n relu(conv_k3_over_n( f1[nb2[v,n], c] ))
//     warp per vertex, lane = channel c. ALL 32 row loads issued upfront
//     into a register array (MLP=32), conv done from registers.
// ============================================================
__global__ void k3_h2(const int* __restrict__ nb2, const float* __restrict__ wv2,
                      const float* __restrict__ bv2, int V) {
    int warp = (blockIdx.x * blockDim.x + threadIdx.x) >> 5;
    int lane = threadIdx.x & 31;
    if (warp >= V) return;
    int idx = nb2[(size_t)warp * 32 + lane];
    if ((unsigned)idx >= (unsigned)V) idx = 0;  // defensive clamp

    float gv[32];
    #pragma unroll
    for (int p = 0; p < 32; p++) {
        int rn = __shfl_sync(0xffffffffu, idx, p);
        gv[p] = __ldg(&g_f1[(size_t)rn * 32 + lane]);  // coalesced 128B row
    }
    float w0 = __ldg(wv2 + 0), w1 = __ldg(wv2 + 1), w2 = __ldg(wv2 + 2);
    float b  = __ldg(bv2);
    float acc = 0.f;
    #pragma unroll
    for (int p = 0; p < 32; p++) {
        float gm = (p > 0)  ? gv[p - 1] : 0.f;
        float gp = (p < 31) ? gv[p + 1] : 0.f;
        acc += fmaxf(w0 * gm + w1 * gv[p] + w2 * gp + b, 0.f);
    }
    g_h2[(size_t)warp * 32 + lane] = acc * (1.0f / 32.0f);
}

// ============================================================
// K4: f2[v,o] = b2[o] + sum_{c,k} h2[v-1+k,c] * w2[o,c,k]
//   4-way channel split, thread owns (o, quarter q). Rolling tap-dots.
//   ulonglong2 row loads (h2 pairs ARE the packed layout -> no pack movs).
//   __launch_bounds__(256,4): force <=64 regs -> 4 blocks/SM.
// ============================================================
#define K4_STRIP 64

__device__ __forceinline__ void k4q_dots(
    int r, int V, int q,
    const unsigned long long* wp0, const unsigned long long* wp1,
    const unsigned long long* wp2,
    float& e0, float& e1, float& e2)
{
    if ((unsigned)r >= (unsigned)V) { e0 = 0.f; e1 = 0.f; e2 = 0.f; return; }
    const ulonglong2* row = (const ulonglong2*)(g_h2 + (size_t)r * 32 + q * 8);
    ulonglong2 ua = __ldg(row);          // channel pairs 8q+{0,1},{2,3}
    ulonglong2 ub = __ldg(row + 1);      // channel pairs 8q+{4,5},{6,7}
    unsigned long long a0 = fma2(ua.x, wp0[0], 0ull);
    unsigned long long a1 = fma2(ua.x, wp1[0], 0ull);
    unsigned long long a2 = fma2(ua.x, wp2[0], 0ull);
    a0 = fma2(ua.y, wp0[1], a0);  a1 = fma2(ua.y, wp1[1], a1);  a2 = fma2(ua.y, wp2[1], a2);
    a0 = fma2(ub.x, wp0[2], a0);  a1 = fma2(ub.x, wp1[2], a1);  a2 = fma2(ub.x, wp2[2], a2);
    a0 = fma2(ub.y, wp0[3], a0);  a1 = fma2(ub.y, wp1[3], a1);  a2 = fma2(ub.y, wp2[3], a2);
    float lo, hi;
    unpack2(a0, lo, hi); e0 = lo + hi;
    unpack2(a1, lo, hi); e1 = lo + hi;
    unpack2(a2, lo, hi); e2 = lo + hi;
}

__global__ __launch_bounds__(256, 4) void k4_f2(const float* __restrict__ w2,
                                                const float* __restrict__ b2, int V) {
    int tid = threadIdx.x;
    int o = tid & 63;
    int q = tid >> 6;                            // channel quarter 0..3

    // wpK[j] = (w2[o][8q+2j][K], w2[o][8q+2j+1][K]); w2 layout [o][c][k]
    const float* wo = w2 + o * 96 + q * 24;
    unsigned long long wp0[4], wp1[4], wp2[4];
    #pragma unroll
    for (int j = 0; j < 4; j++) {
        wp0[j] = pack2(__ldg(wo + 6 * j + 0), __ldg(wo + 6 * j + 3));
        wp1[j] = pack2(__ldg(wo + 6 * j + 1), __ldg(wo + 6 * j + 4));
        wp2[j] = pack2(__ldg(wo + 6 * j + 2), __ldg(wo + 6 * j + 5));
    }
    float bias = (q == 0) ? __ldg(b2 + o) : 0.f;
    float* outbuf = g_f2p[q];

    int vbase = blockIdx.x * K4_STRIP;
    if (vbase >= V) return;
    int vend = vbase + K4_STRIP; if (vend > V) vend = V;

    // Prime: d0m = tap0-dot(row vbase-1); d0c/d1c = tap0/tap1 dots(row vbase)
    float d0m, d0c, d1c, tA, tB;
    k4q_dots(vbase - 1, V, q, wp0, wp1, wp2, d0m, tA, tB);
    k4q_dots(vbase,     V, q, wp0, wp1, wp2, d0c, d1c, tB);

    #pragma unroll 4
    for (int v = vbase; v < vend; v++) {
        float e0, e1, e2;
        k4q_dots(v + 1, V, q, wp0, wp1, wp2, e0, e1, e2);
        outbuf[(size_t)v * 64 + o] = d0m + d1c + e2 + bias;
        d0m = d0c; d0c = e0; d1c = e1;
    }
}

// ============================================================
// K5: logits = f2 @ wfc.T + bfc ; softmax
//     8-vertex tile (halves softmax/staging overhead per vertex).
//     Staging read sums the 4 k4 partial buffers.
//     Inner loop: LDS.128 + FFMA2 (fma-pipe bound).
// ============================================================
__global__ __launch_bounds__(256, 1) void k5_fc(const float* __restrict__ wfc,
                                                const float* __restrict__ bfc,
                                                float* __restrict__ out, int V) {
    __shared__ __align__(16) unsigned long long f2s[8 * 64];  // duplicated f2
    __shared__ float smax[8 * 8];
    __shared__ float ssum[8 * 8];
    int tid  = threadIdx.x;
    int lane = tid & 31, warp = tid >> 5;

    unsigned long long wpair[64];
    const float* wa = wfc + (2 * tid) * 64;
    const float* wb = wfc + (2 * tid + 1) * 64;
    #pragma unroll
    for (int c = 0; c < 64; c++) wpair[c] = pack2(__ldg(wa + c), __ldg(wb + c));
    unsigned long long bp = pack2(__ldg(bfc + 2 * tid), __ldg(bfc + 2 * tid + 1));

    for (int vbase = blockIdx.x * 8; vbase < V; vbase += gridDim.x * 8) {
        // staging: 512 values, 2 per thread
        #pragma unroll
        for (int rep = 0; rep < 2; rep++) {
            int i = tid + rep * 256;             // i = lv*64 + lc
            int lv = i >> 6, lc = i & 63;
            int vl = vbase + lv;
            float fv = 0.f;
            if (vl < V) {
                size_t ix = (size_t)vl * 64 + lc;
                fv = g_f2p[0][ix] + g_f2p[1][ix] + g_f2p[2][ix] + g_f2p[3][ix];
            }
            f2s[i] = pack2(fv, fv);
        }
        __syncthreads();

        unsigned long long acc[8];
        #pragma unroll
        for (int t = 0; t < 8; t++) acc[t] = bp;
        const ulonglong2* f2s2 = (const ulonglong2*)f2s;
        #pragma unroll
        for (int c2 = 0; c2 < 32; c2++) {
            #pragma unroll
            for (int t = 0; t < 8; t++) {
                ulonglong2 qv = f2s2[t * 32 + c2];
                acc[t] = fma2(wpair[2 * c2], qv.x, acc[t]);
                acc[t] = fma2(wpair[2 * c2 + 1], qv.y, acc[t]);
            }
        }
        float l0[8], l1[8];
        #pragma unroll
        for (int t = 0; t < 8; t++) unpack2(acc[t], l0[t], l1[t]);

        // phase A: per-warp max
        #pragma unroll
        for (int t = 0; t < 8; t++) {
            float m = fmaxf(l0[t], l1[t]);
            #pragma unroll
            for (int s = 16; s > 0; s >>= 1) m = fmaxf(m, __shfl_xor_sync(0xffffffffu, m, s));
            if (lane == 0) smax[t * 8 + warp] = m;
        }
        __syncthreads();

        // phase B: block max -> exp -> per-warp sum
        float e0[8], e1[8];
        #pragma unroll
        for (int t = 0; t < 8; t++) {
            float bm = smax[t * 8];
            #pragma unroll
            for (int j = 1; j < 8; j++) bm = fmaxf(bm, smax[t * 8 + j]);
            e0[t] = __expf(l0[t] - bm);
            e1[t] = __expf(l1[t] - bm);
            float s = e0[t] + e1[t];
            #pragma unroll
            for (int sh = 16; sh > 0; sh >>= 1) s += __shfl_xor_sync(0xffffffffu, s, sh);
            if (lane == 0) ssum[t * 8 + warp] = s;
        }
        __syncthreads();

        // phase C: block sum -> normalize -> store (float2, coalesced)
        #pragma unroll
        for (int t = 0; t < 8; t++) {
            int v = vbase + t;
            if (v < V) {
                float bs = ssum[t * 8];
                #pragma unroll
                for (int j = 1; j < 8; j++) bs += ssum[t * 8 + j];
                float inv = 1.0f / bs;
                ((float2*)out)[(size_t)v * 256 + tid] = make_float2(e0[t] * inv, e1[t] * inv);
            }
        }
        __syncthreads();
    }
}

// ============================================================
// Launch: bind inputs BY ELEMENT COUNT (robust to metadata ordering).
// 4 launches: k12, k3, k4, k5  (capture slot 4 -> k5 gets profiled)
// ============================================================
extern "C" void kernel_launch(void* const* d_in, const int* in_sizes, int n_in,
                              void* d_out, int out_size) {
    long long mx = 0;
    for (int i = 0; i < n_in; i++) if ((long long)in_sizes[i] > mx) mx = in_sizes[i];
    int V = (int)(mx / 32);
    if (V > V_MAX) V = V_MAX;

    const float *vp = 0, *wv1 = 0, *bv1 = 0, *w1 = 0, *b1 = 0;
    const float *wv2 = 0, *bv2 = 0, *w2 = 0, *b2 = 0, *wfc = 0, *bfc = 0;
    const int *nb1 = 0, *nb2 = 0;

    int nb_seen = 0, wv_seen = 0, bv_seen = 0;
    for (int i = 0; i < n_in; i++) {
        long long s = in_sizes[i];
        const void* p = d_in[i];
        if (s == mx)            { if (nb_seen++ == 0) nb1 = (const int*)p; else nb2 = (const int*)p; }
        else if (s == V)        { vp  = (const float*)p; }
        else if (s == 3)        { if (wv_seen++ == 0) wv1 = (const float*)p; else wv2 = (const float*)p; }
        else if (s == 1)        { if (bv_seen++ == 0) bv1 = (const float*)p; else bv2 = (const float*)p; }
        else if (s == 96)       { w1  = (const float*)p; }
        else if (s == 32)       { b1  = (const float*)p; }
        else if (s == 6144)     { w2  = (const float*)p; }
        else if (s == 64)       { b2  = (const float*)p; }
        else if (s == 32768)    { wfc = (const float*)p; }
        else if (s == 512)      { bfc = (const float*)p; }
    }
    if (!vp || !nb1 || !nb2 || !wv1 || !bv1 || !w1 || !b1 ||
        !wv2 || !bv2 || !w2 || !b2 || !wfc || !bfc) return;
    float* out = (float*)d_out;

    int k12Blocks = (V + K12_VPB - 1) / K12_VPB;
    int warpBlocks = (V + 7) / 8;                 // 8 warps (256 thr) per block
    int k4Blocks = (V + K4_STRIP - 1) / K4_STRIP;
    k12  <<<k12Blocks, 320>>>(vp, nb1, wv1, bv1, w1, b1, V);
    k3_h2<<<warpBlocks, 256>>>(nb2, wv2, bv2, V);
    k4_f2<<<k4Blocks, 256>>>(w2, b2, V);
    k5_fc<<<148, 256>>>(wfc, bfc, out, V);
}